// round 16
// baseline (speedup 1.0000x reference)
#include <cuda_runtime.h>
#include <cuda_fp16.h>
#include <cstdint>

// Problem constants
#define B_   32
#define I_   512
#define F_   321
#define O_   720
#define OPAD 768
#define R_   (B_ * I_)
#define EPSV 1e-5f

// GEMM tiling
#define OT   128              // o rows per CTA
#define KC   32               // k per chunk (fine-grained, 2-deep reg pipeline)
#define NCH  (I_ / KC)        // 16 chunks

// smem layout
// x row: 512 fp16 = 1024B + 16B pad -> word stride 260 (≡4 mod 32, conflict-free)
#define XROWB  1040
#define XBYTES (B_ * XROWB)            // 33280
// W row: 32 fp16 = 64B + 16B pad -> word stride 20 (r*20+q mod 32 all-distinct)
#define WROWB  80
#define WBYTES (OT * WROWB)            // 10240 per buffer
#define SM_XH  0
#define SM_WH  XBYTES
#define SMEM_BYTES (XBYTES + 2 * WBYTES)   // 53760 -> 2 CTAs/SM

// device scratch
__device__ __align__(16) __half g_xh[(size_t)F_ * R_];
__device__ __align__(16) float  g_out[(size_t)F_ * OPAD * B_];

// ---- helpers ----
__device__ __forceinline__ uint32_t smem_u32(const void* p) {
    uint32_t a;
    asm("{ .reg .u64 t; cvta.to.shared.u64 t, %1; cvt.u32.u64 %0, t; }"
        : "=r"(a) : "l"(p));
    return a;
}
__device__ __forceinline__ void cp16(uint32_t dst, const void* src) {
    asm volatile("cp.async.cg.shared.global [%0], [%1], 16;\n" :: "r"(dst), "l"(src));
}
__device__ __forceinline__ void cp_commit() {
    asm volatile("cp.async.commit_group;\n");
}
template <int N>
__device__ __forceinline__ void cp_wait() {
    asm volatile("cp.async.wait_group %0;\n" :: "n"(N));
}
__device__ __forceinline__ void mma16816(float* acc, const uint32_t a[4],
                                         uint32_t b0, uint32_t b1) {
    asm volatile(
        "mma.sync.aligned.m16n8k16.row.col.f32.f16.f16.f32 "
        "{%0,%1,%2,%3}, {%4,%5,%6,%7}, {%8,%9}, {%0,%1,%2,%3};\n"
        : "+f"(acc[0]), "+f"(acc[1]), "+f"(acc[2]), "+f"(acc[3])
        : "r"(a[0]), "r"(a[1]), "r"(a[2]), "r"(a[3]), "r"(b0), "r"(b1));
}
__device__ __forceinline__ uint32_t h2u(__half2 h) {
    return *reinterpret_cast<uint32_t*>(&h);
}

// ---------------------------------------------------------------------------
// Kernel 1: normalize + transpose + fp16 convert
// x[b,i,f] -> g_xh[f, b*512+i]
// ---------------------------------------------------------------------------
__global__ void norm_transpose_kernel(const float* __restrict__ x,
                                      const float* __restrict__ gamma,
                                      const float* __restrict__ beta,
                                      const float* __restrict__ rmean,
                                      const float* __restrict__ rvar)
{
    __shared__ float s[32][33];
    const int f0 = blockIdx.x * 32;
    const int r0 = blockIdx.y * 32;
    const int tx = threadIdx.x, ty = threadIdx.y;

    const int f = f0 + tx;
    float inv = 0.f, shift = 0.f;
    if (f < F_) {
        inv   = gamma[f] * rsqrtf(rvar[f] + EPSV);
        shift = beta[f] - rmean[f] * inv;
    }
#pragma unroll
    for (int k = 0; k < 4; k++) {
        const int rl = ty + k * 8;
        float v = (f < F_) ? x[(size_t)(r0 + rl) * F_ + f] : 0.f;
        s[rl][tx] = v * inv + shift;
    }
    __syncthreads();
#pragma unroll
    for (int k = 0; k < 4; k++) {
        const int fl = ty + k * 8;
        const int ff = f0 + fl;
        if (ff < F_)
            g_xh[(size_t)ff * R_ + (size_t)(r0 + tx)] = __float2half_rn(s[tx][fl]);
    }
}

// ---------------------------------------------------------------------------
// Kernel 2: fp16 mma.sync GEMM per (o-tile, f), 2-chunk-deep W reg pipeline.
// D[o(128), b(32)] = sum_i W[f,o,i] * xn[f,b,i]; writes g_out[f][o][b]+bias.
// ---------------------------------------------------------------------------
__global__ void __launch_bounds__(256, 2)
gemm_kernel(const float* __restrict__ W,
            const float* __restrict__ bias)
{
    extern __shared__ char smem[];
    const uint32_t sb = smem_u32(smem);
    const int tid  = threadIdx.x;
    const int wid  = tid >> 5;
    const int lane = tid & 31;
    const int r    = lane >> 2;        // 0..7
    const int q    = lane & 3;         // 0..3

    const int f  = blockIdx.y;
    const int ot = blockIdx.x * OT;

    const float* __restrict__ Wf = W + (size_t)f * (O_ * I_);
    const __half* __restrict__ xh = g_xh + (size_t)f * R_;

    // x tile (32 x 512 fp16) -> smem via cp.async (single group)
#pragma unroll
    for (int p = tid; p < B_ * 64; p += 256) {           // 2048 x 16B
        const int b = p >> 6, u = p & 63;
        cp16(sb + SM_XH + (uint32_t)(b * XROWB + u * 16), xh + b * 512 + u * 8);
    }
    cp_commit();

    // W register staging: thread owns (rb = tid>>3, k8 = tid&7);
    // rows rb + 32*jj, one float4 each -> fully coalesced 128B LDG runs.
    const int rb = tid >> 3, k8 = tid & 7;
    float4 wreg[2][4];                                   // 2 chunk sets
    auto ldg_chunk = [&](int c, int set) {
        const float* src = Wf + (size_t)(c * KC) + k8 * 4;
#pragma unroll
        for (int jj = 0; jj < 4; jj++) {
            int o = ot + jj * 32 + rb;
            if (o > O_ - 1) o = O_ - 1;
            wreg[set][jj] = *reinterpret_cast<const float4*>(src + (size_t)o * I_);
        }
    };
    auto stw = [&](int set, int buf) {
        char* dst = smem + SM_WH + buf * WBYTES;
#pragma unroll
        for (int jj = 0; jj < 4; jj++) {
            const int row = jj * 32 + rb;
            const __half2 h0 = __floats2half2_rn(wreg[set][jj].x, wreg[set][jj].y);
            const __half2 h1 = __floats2half2_rn(wreg[set][jj].z, wreg[set][jj].w);
            *reinterpret_cast<uint2*>(dst + row * WROWB + k8 * 8) =
                make_uint2(h2u(h0), h2u(h1));
        }
    };

    ldg_chunk(0, 0);
    ldg_chunk(1, 1);

    float acc[4][4];
#pragma unroll
    for (int n = 0; n < 4; n++)
#pragma unroll
        for (int j = 0; j < 4; j++) acc[n][j] = 0.f;

    const uint32_t* xt = reinterpret_cast<const uint32_t*>(smem + SM_XH);
    const int arow = wid * 16 + r;                       // warp A row (+8)

#pragma unroll 1
    for (int c = 0; c < NCH; c++) {
        const int pb = c & 1;
        stw(pb, pb);                     // consume reg set pb into buffer pb
        if (c + 2 < NCH) ldg_chunk(c + 2, pb);  // refill set; lands 2 iters out
        if (c == 0) cp_wait<0>();        // x tile resident
        __syncthreads();

        const uint32_t* wt = reinterpret_cast<const uint32_t*>(
            smem + SM_WH + pb * WBYTES);
        const int xko = c * (KC / 2);    // k word offset into x rows
#pragma unroll
        for (int ks = 0; ks < 2; ks++) {
            const int aw = arow * (WROWB / 4) + ks * 8 + q;
            uint32_t a[4];
            a[0] = wt[aw];
            a[1] = wt[aw + 8 * (WROWB / 4)];
            a[2] = wt[aw + 4];
            a[3] = wt[aw + 8 * (WROWB / 4) + 4];
#pragma unroll
            for (int nt = 0; nt < 4; nt++) {
                const int bw = (nt * 8 + r) * (XROWB / 4) + xko + ks * 8 + q;
                mma16816(acc[nt], a, xt[bw], xt[bw + 4]);
            }
        }
        // buffer pb is re-written by stw(c+2) only after the sync of iter c+1:
        // every reader (this mma) is separated from that writer by >=1 sync.
    }

    // Epilogue: g_out[f][o][b] += bias
    {
        const int o0  = ot + arow;
        const int ob0 = (o0     < O_) ? o0     : O_ - 1;
        const int ob1 = (o0 + 8 < O_) ? o0 + 8 : O_ - 1;
        const float bv0 = bias[(size_t)f * O_ + ob0];
        const float bv1 = bias[(size_t)f * O_ + ob1];
        float* base0 = g_out + ((size_t)f * OPAD + o0)     * B_ + q * 2;
        float* base1 = g_out + ((size_t)f * OPAD + o0 + 8) * B_ + q * 2;
#pragma unroll
        for (int nt = 0; nt < 4; nt++) {
            *reinterpret_cast<float2*>(base0 + nt * 8) =
                make_float2(acc[nt][0] + bv0, acc[nt][1] + bv0);
            *reinterpret_cast<float2*>(base1 + nt * 8) =
                make_float2(acc[nt][2] + bv1, acc[nt][3] + bv1);
        }
    }
}

// ---------------------------------------------------------------------------
// Kernel 3: g_out[f][o][b] -> out[b][o][f], 4 o's per CTA
// ---------------------------------------------------------------------------
__global__ void out_transpose_kernel(float* __restrict__ out)
{
    __shared__ float s[4][32][33];
    const int o0 = blockIdx.x * 4;
    const int f0 = blockIdx.y * 32;
    const int tx = threadIdx.x, ty = threadIdx.y;

    const int f = f0 + ty;
#pragma unroll
    for (int oo = 0; oo < 4; oo++) {
        if (f < F_)
            s[oo][ty][tx] = g_out[((size_t)f * OPAD + o0 + oo) * B_ + tx];
    }
    __syncthreads();

    const int ff = f0 + tx;
    if (ff < F_) {
#pragma unroll
        for (int oo = 0; oo < 4; oo++) {
            out[(size_t)ty * (O_ * F_) + (size_t)(o0 + oo) * F_ + ff] =
                s[oo][tx][ty];
        }
    }
}

// ---------------------------------------------------------------------------
// Launch
// ---------------------------------------------------------------------------
extern "C" void kernel_launch(void* const* d_in, const int* in_sizes, int n_in,
                              void* d_out, int out_size)
{
    const float* x     = (const float*)d_in[0];
    const float* W     = (const float*)d_in[1];
    const float* bias  = (const float*)d_in[2];
    const float* gamma = (const float*)d_in[3];
    const float* beta  = (const float*)d_in[4];
    const float* rmean = (const float*)d_in[5];
    const float* rvar  = (const float*)d_in[6];
    float* out = (float*)d_out;
    (void)in_sizes; (void)n_in; (void)out_size;

    cudaFuncSetAttribute(gemm_kernel,
                         cudaFuncAttributeMaxDynamicSharedMemorySize, SMEM_BYTES);

    norm_transpose_kernel<<<dim3(11, R_ / 32), dim3(32, 8)>>>(x, gamma, beta,
                                                              rmean, rvar);
    gemm_kernel<<<dim3(OPAD / OT, F_), 256, SMEM_BYTES>>>(W, bias);
    out_transpose_kernel<<<dim3(O_ / 4, 11), dim3(32, 32)>>>(out);
}